// round 1
// baseline (speedup 1.0000x reference)
#include <cuda_runtime.h>
#include <math.h>
#include <stdint.h>

#define BB 64
#define SS 40
#define TD 39
#define EE 256
#define UU 1024
#define VV 8192
#define G3 3072

// Scratch (device globals; no allocation allowed)
static __device__ float g_gxe[BB * SS * G3];      // encoder x@Wx + b0
static __device__ float g_gxd[BB * TD * G3];      // decoder xt@Wx_bot + b0
static __device__ float g_enc_out[BB * SS * UU];  // encoder hidden sequence
static __device__ float g_P[BB * SS * G3];        // enc_out @ dec_Wx[:U]
static __device__ float g_hdec[BB * TD * UU];     // decoder hidden per step

// ---------------------------------------------------------------------------
// packed fp32x2 FMA (2x FFMA pipe throughput on sm_103a)
// ---------------------------------------------------------------------------
__device__ __forceinline__ float2 fma2(float2 a, float2 b, float2 c) {
    unsigned long long ua, ub, uc;
    memcpy(&ua, &a, 8); memcpy(&ub, &b, 8); memcpy(&uc, &c, 8);
    asm("fma.rn.f32x2 %0, %1, %2, %0;" : "+l"(uc) : "l"(ua), "l"(ub));
    float2 r; memcpy(&r, &uc, 8);
    return r;
}

__device__ __forceinline__ float sigmoidf_(float x) {
    return 1.0f / (1.0f + expf(-x));
}

// ---------------------------------------------------------------------------
// Generic fp32 GEMM:  C[M,N] = A[M,K] @ W[K,N] (+ bias)
// Optional row gather: A row m = emb[idx[(m/TT)*stride + m%TT]]
// BM=64, BN=64, BK=16, 256 threads, 4x4 micro-tile via f32x2 (rows paired)
// M,N multiples of 64; K multiple of 16.
// ---------------------------------------------------------------------------
#define Bب 0
__global__ __launch_bounds__(256) void gemm_f32(
    const float* __restrict__ A,
    const float* __restrict__ emb, const int* __restrict__ idx,
    int idxTT, int idxStride, int lda,
    const float* __restrict__ W, int ldw,
    const float* __restrict__ bias,
    float* __restrict__ C, int M, int N, int K)
{
    __shared__ __align__(16) float As[16][64];
    __shared__ float2 Wd[16][64];

    const int tid = threadIdx.x;
    const int bm = blockIdx.y * 64;
    const int bn = blockIdx.x * 64;

    const int m_l = tid & 63;      // loader row/col index
    const int kq  = tid >> 6;      // 0..3

    const int m = bm + m_l;
    const float* arow;
    if (emb) {
        int r = idx[(m / idxTT) * idxStride + (m % idxTT)];
        arow = emb + (size_t)r * lda;
    } else {
        arow = A + (size_t)m * lda;
    }

    const int tx = tid & 15, ty = tid >> 4;
    const int r0 = ty * 4, c0 = tx * 4;

    float2 acc[2][4];
#pragma unroll
    for (int p = 0; p < 2; p++)
#pragma unroll
        for (int c = 0; c < 4; c++) acc[p][c] = make_float2(0.f, 0.f);

    for (int k0 = 0; k0 < K; k0 += 16) {
        // load A chunk (4 consecutive k per thread, vectorized)
        float4 av = *reinterpret_cast<const float4*>(arow + k0 + kq * 4);
        // load W chunk (4 k-rows per thread, coalesced over n)
        float w0 = W[(size_t)(k0 + kq * 4 + 0) * ldw + bn + m_l];
        float w1 = W[(size_t)(k0 + kq * 4 + 1) * ldw + bn + m_l];
        float w2 = W[(size_t)(k0 + kq * 4 + 2) * ldw + bn + m_l];
        float w3 = W[(size_t)(k0 + kq * 4 + 3) * ldw + bn + m_l];
        __syncthreads();
        As[kq * 4 + 0][m_l] = av.x;
        As[kq * 4 + 1][m_l] = av.y;
        As[kq * 4 + 2][m_l] = av.z;
        As[kq * 4 + 3][m_l] = av.w;
        Wd[kq * 4 + 0][m_l] = make_float2(w0, w0);
        Wd[kq * 4 + 1][m_l] = make_float2(w1, w1);
        Wd[kq * 4 + 2][m_l] = make_float2(w2, w2);
        Wd[kq * 4 + 3][m_l] = make_float2(w3, w3);
        __syncthreads();
#pragma unroll
        for (int k = 0; k < 16; k++) {
            float2 a0 = *reinterpret_cast<const float2*>(&As[k][r0]);
            float2 a1 = *reinterpret_cast<const float2*>(&As[k][r0 + 2]);
#pragma unroll
            for (int c = 0; c < 4; c++) {
                float2 wv = Wd[k][c0 + c];
                acc[0][c] = fma2(a0, wv, acc[0][c]);
                acc[1][c] = fma2(a1, wv, acc[1][c]);
            }
        }
    }

#pragma unroll
    for (int c = 0; c < 4; c++) {
        int n = bn + c0 + c;
        float bv = bias ? bias[n] : 0.f;
        C[(size_t)(bm + r0 + 0) * N + n] = acc[0][c].x + bv;
        C[(size_t)(bm + r0 + 1) * N + n] = acc[0][c].y + bv;
        C[(size_t)(bm + r0 + 2) * N + n] = acc[1][c].x + bv;
        C[(size_t)(bm + r0 + 3) * N + n] = acc[1][c].y + bv;
    }
}

// ---------------------------------------------------------------------------
// Encoder step: gh = h_prev @ enc_Wh (+b1) fused with GRU update.
// grid = 256 blocks (4 u-cols each), 128 threads.
// Each thread: 1 u-col x 1 batch-row-pair, 3 gate accumulators (f32x2).
// Reads h_prev from [b*hp_stride + k]; writes h' to out_base[b*out_stride+u].
// t=0 (has_h=0): gh = b1, h_old = 0, no GEMM.
// ---------------------------------------------------------------------------
__global__ __launch_bounds__(128) void enc_step_kernel(
    const float* __restrict__ h_prev, int hp_stride, int has_h,
    const float* __restrict__ gx_base, int gx_stride,
    const float* __restrict__ Wh,
    const float* __restrict__ b1,
    float* __restrict__ out_base, int out_stride)
{
    __shared__ float2 h2s[32][32];   // [k][row-pair]
    __shared__ float2 wds[32][12];   // [k][gate*4 + u_l], duplicated

    const int tid = threadIdx.x;
    const int u_l = tid & 3;
    const int p   = tid >> 2;        // 0..31 -> rows 2p, 2p+1
    const int u   = blockIdx.x * 4 + u_l;

    float2 az = make_float2(0.f, 0.f), ar = az, ac = az;

    if (has_h) {
        for (int k0 = 0; k0 < UU; k0 += 32) {
#pragma unroll
            for (int e = tid; e < 1024; e += 128) {
                int kk = e & 31, pp = e >> 5;
                h2s[kk][pp] = make_float2(h_prev[(size_t)(2 * pp) * hp_stride + k0 + kk],
                                          h_prev[(size_t)(2 * pp + 1) * hp_stride + k0 + kk]);
            }
            for (int e = tid; e < 384; e += 128) {
                int kk = e / 12, cc = e % 12;
                int g = cc >> 2, uu = cc & 3;
                float w = Wh[(size_t)(k0 + kk) * G3 + g * UU + blockIdx.x * 4 + uu];
                wds[kk][cc] = make_float2(w, w);
            }
            __syncthreads();
#pragma unroll
            for (int kk = 0; kk < 32; kk++) {
                float2 h2 = h2s[kk][p];
                az = fma2(h2, wds[kk][u_l], az);
                ar = fma2(h2, wds[kk][4 + u_l], ar);
                ac = fma2(h2, wds[kk][8 + u_l], ac);
            }
            __syncthreads();
        }
    }

    float b1z = b1[u], b1r = b1[UU + u], b1c = b1[2 * UU + u];
#pragma unroll
    for (int half = 0; half < 2; half++) {
        int b = 2 * p + half;
        float gz = half ? az.y : az.x;
        float gr = half ? ar.y : ar.x;
        float gc = half ? ac.y : ac.x;
        const float* gx = gx_base + (size_t)b * gx_stride;
        float hold = has_h ? h_prev[(size_t)b * hp_stride + u] : 0.f;
        float z = sigmoidf_(gx[u] + gz + b1z);
        float r = sigmoidf_(gx[UU + u] + gr + b1r);
        float c = tanhf(gx[2 * UU + u] + r * (gc + b1c));
        out_base[(size_t)b * out_stride + u] = z * hold + (1.f - z) * c;
    }
}

// ---------------------------------------------------------------------------
// Decoder step (one block per batch b, 256 threads):
//   scores = h . enc_out ; softmax ; gx_ctx = sum_s w_s * P[b,s,:] ; GRU(h0=0)
// ---------------------------------------------------------------------------
__global__ __launch_bounds__(256) void dec_step_kernel(
    const float* __restrict__ h_prev, int hp_stride,
    const float* __restrict__ enc_out,
    const float* __restrict__ P,
    const float* __restrict__ gxd_t, int gxd_stride,
    const float* __restrict__ db1,
    float* __restrict__ h_out, int ho_stride)
{
    const int b = blockIdx.x;
    const int tid = threadIdx.x;
    const int warp = tid >> 5, lane = tid & 31;

    __shared__ float wsm[SS];
    __shared__ float gxc[G3];

    // Phase 1: attention scores (warp w handles s = w*5 .. w*5+4)
    {
        const float* hb = h_prev + (size_t)b * hp_stride;
        const float* eb = enc_out + (size_t)b * SS * UU;
        float acc[5] = {0.f, 0.f, 0.f, 0.f, 0.f};
#pragma unroll 4
        for (int i = 0; i < 32; i++) {
            int uidx = lane + 32 * i;
            float hv = hb[uidx];
#pragma unroll
            for (int q = 0; q < 5; q++)
                acc[q] += hv * eb[(size_t)(warp * 5 + q) * UU + uidx];
        }
#pragma unroll
        for (int q = 0; q < 5; q++) {
            float v = acc[q];
            for (int o = 16; o; o >>= 1) v += __shfl_xor_sync(0xffffffffu, v, o);
            if (lane == 0) wsm[warp * 5 + q] = v;
        }
    }
    __syncthreads();

    // Phase 1b: softmax over 40 (single thread; tiny)
    if (tid == 0) {
        float mx = -1e30f;
        for (int s = 0; s < SS; s++) mx = fmaxf(mx, wsm[s]);
        float sm = 0.f;
        for (int s = 0; s < SS; s++) { float e = expf(wsm[s] - mx); wsm[s] = e; sm += e; }
        float inv = 1.f / sm;
        for (int s = 0; s < SS; s++) wsm[s] *= inv;
    }
    __syncthreads();

    // Phase 2: gx_ctx[n] = sum_s w_s * P[b,s,n]   (12 independent chains/thread)
    {
        const float* Pb = P + (size_t)b * SS * G3;
        float a[12];
#pragma unroll
        for (int i = 0; i < 12; i++) a[i] = 0.f;
        for (int s = 0; s < SS; s++) {
            float w = wsm[s];
            const float* row = Pb + (size_t)s * G3;
#pragma unroll
            for (int i = 0; i < 12; i++)
                a[i] += w * row[tid + i * 256];
        }
#pragma unroll
        for (int i = 0; i < 12; i++) gxc[tid + i * 256] = a[i];
    }
    __syncthreads();

    // Phase 3: GRU with h0 = 0  ->  h_new = (1-z)*c
    {
        const float* gx = gxd_t + (size_t)b * gxd_stride;
        float* ho = h_out + (size_t)b * ho_stride;
#pragma unroll
        for (int i = 0; i < 4; i++) {
            int u = tid + i * 256;
            float z = sigmoidf_(gxc[u] + gx[u] + db1[u]);
            float r = sigmoidf_(gxc[UU + u] + gx[UU + u] + db1[UU + u]);
            float c = tanhf(gxc[2 * UU + u] + gx[2 * UU + u] + r * db1[2 * UU + u]);
            ho[u] = (1.f - z) * c;
        }
    }
}

// ---------------------------------------------------------------------------
extern "C" void kernel_launch(void* const* d_in, const int* in_sizes, int n_in,
                              void* d_out, int out_size)
{
    const int*   inp     = (const int*)d_in[0];
    const int*   targ    = (const int*)d_in[1];
    const float* enc_emb = (const float*)d_in[2];
    const float* enc_Wx  = (const float*)d_in[3];
    const float* enc_Wh  = (const float*)d_in[4];
    const float* enc_b   = (const float*)d_in[5];
    const float* dec_emb = (const float*)d_in[6];
    const float* dec_Wx  = (const float*)d_in[7];
    // d_in[8] = dec_Wh: provably unused (decoder GRU hidden input is zeros)
    const float* dec_b   = (const float*)d_in[9];
    const float* fc_W    = (const float*)d_in[10];
    const float* fc_b    = (const float*)d_in[11];
    float* out = (float*)d_out;

    float *gxe, *gxd, *enc_out, *P, *hdec;
    cudaGetSymbolAddress((void**)&gxe,     g_gxe);
    cudaGetSymbolAddress((void**)&gxd,     g_gxd);
    cudaGetSymbolAddress((void**)&enc_out, g_enc_out);
    cudaGetSymbolAddress((void**)&P,       g_P);
    cudaGetSymbolAddress((void**)&hdec,    g_hdec);

    // 1) Encoder gx for all timesteps: (B*S,3U) = emb[inp] @ enc_Wx + b0
    gemm_f32<<<dim3(G3 / 64, (BB * SS) / 64), 256>>>(
        nullptr, enc_emb, inp, SS, SS, EE,
        enc_Wx, G3, enc_b, gxe, BB * SS, G3, EE);

    // 2) Decoder xt-part gx for all steps: emb[targ[:, :-1]] @ dec_Wx[U:] + b0
    gemm_f32<<<dim3(G3 / 64, (BB * TD) / 64), 256>>>(
        nullptr, dec_emb, targ, TD, SS, EE,
        dec_Wx + (size_t)UU * G3, G3, dec_b, gxd, BB * TD, G3, EE);

    // 3) Encoder recurrence (sequential)
    for (int t = 0; t < SS; t++) {
        const float* hp = (t == 0) ? nullptr : (enc_out + (size_t)(t - 1) * UU);
        enc_step_kernel<<<256, 128>>>(
            hp, SS * UU, (t > 0) ? 1 : 0,
            gxe + (size_t)t * G3, SS * G3,
            enc_Wh, enc_b + G3,
            enc_out + (size_t)t * UU, SS * UU);
    }

    // 4) P = enc_out @ dec_Wx[:U]   (factored attention-context projection)
    gemm_f32<<<dim3(G3 / 64, (BB * SS) / 64), 256>>>(
        enc_out, nullptr, nullptr, 1, 1, UU,
        dec_Wx, G3, nullptr, P, BB * SS, G3, UU);

    // 5) Decoder recurrence (sequential, cheap: attention + weighted sum + GRU)
    for (int t = 0; t < TD; t++) {
        const float* hp;
        int hps;
        if (t == 0) { hp = enc_out + (size_t)(SS - 1) * UU; hps = SS * UU; }
        else        { hp = hdec + (size_t)(t - 1) * UU;     hps = TD * UU; }
        dec_step_kernel<<<BB, 256>>>(
            hp, hps, enc_out, P,
            gxd + (size_t)t * G3, TD * G3,
            dec_b + G3,
            hdec + (size_t)t * UU, TD * UU);
    }

    // 6) Batched output projection: preds = hdec @ fc_W + fc_b
    gemm_f32<<<dim3(VV / 64, (BB * TD) / 64), 256>>>(
        hdec, nullptr, nullptr, 1, 1, UU,
        fc_W, VV, fc_b, out, BB * TD, VV, UU);
}

// round 5
// speedup vs baseline: 1.3508x; 1.3508x over previous
#include <cuda_runtime.h>
#include <math.h>
#include <stdint.h>
#include <string.h>

#define BB 64
#define SS 40
#define TD 39
#define EE 256
#define UU 1024
#define VV 8192
#define G3 3072

// Scratch (device globals; no allocation allowed)
static __device__ float g_gxe[BB * SS * G3];      // encoder x@Wx + b0
static __device__ float g_gxd[BB * TD * G3];      // decoder xt@Wx_bot + b0
static __device__ float g_enc_out[BB * SS * UU];  // encoder hidden sequence
static __device__ float g_P[BB * SS * G3];        // enc_out @ dec_Wx[:U]
static __device__ float g_hdec[BB * TD * UU];     // decoder hidden per step
static __device__ unsigned g_bar[2];              // [0]=count, [1]=release epoch

// ---------------------------------------------------------------------------
// packed fp32x2 FMA (2x FFMA pipe throughput on sm_103a)
// ---------------------------------------------------------------------------
__device__ __forceinline__ float2 fma2(float2 a, float2 b, float2 c) {
    unsigned long long ua, ub, uc;
    memcpy(&ua, &a, 8); memcpy(&ub, &b, 8); memcpy(&uc, &c, 8);
    asm("fma.rn.f32x2 %0, %1, %2, %0;" : "+l"(uc) : "l"(ua), "l"(ub));
    float2 r; memcpy(&r, &uc, 8);
    return r;
}

__device__ __forceinline__ float sigmoidf_(float x) {
    return 1.0f / (1.0f + expf(-x));
}

// ---------------------------------------------------------------------------
// Generic fp32 GEMM:  C[M,N] = A[M,K] @ W[K,N] (+ bias)
// Optional row gather: A row m = emb[idx[(m/TT)*stride + m%TT]]
// BM=64, BN=64, BK=16, 256 threads, 4x4 micro-tile via f32x2 (rows paired)
// ---------------------------------------------------------------------------
__global__ __launch_bounds__(256) void gemm_f32(
    const float* __restrict__ A,
    const float* __restrict__ emb, const int* __restrict__ idx,
    int idxTT, int idxStride, int lda,
    const float* __restrict__ W, int ldw,
    const float* __restrict__ bias,
    float* __restrict__ C, int M, int N, int K)
{
    __shared__ __align__(16) float As[16][64];
    __shared__ float2 Wd[16][64];

    const int tid = threadIdx.x;
    const int bm = blockIdx.y * 64;
    const int bn = blockIdx.x * 64;

    const int m_l = tid & 63;      // loader row/col index
    const int kq  = tid >> 6;      // 0..3

    const int m = bm + m_l;
    const float* arow;
    if (emb) {
        int r = idx[(m / idxTT) * idxStride + (m % idxTT)];
        arow = emb + (size_t)r * lda;
    } else {
        arow = A + (size_t)m * lda;
    }

    const int tx = tid & 15, ty = tid >> 4;
    const int r0 = ty * 4, c0 = tx * 4;

    float2 acc[2][4];
#pragma unroll
    for (int p = 0; p < 2; p++)
#pragma unroll
        for (int c = 0; c < 4; c++) acc[p][c] = make_float2(0.f, 0.f);

    for (int k0 = 0; k0 < K; k0 += 16) {
        float4 av = *reinterpret_cast<const float4*>(arow + k0 + kq * 4);
        float w0 = W[(size_t)(k0 + kq * 4 + 0) * ldw + bn + m_l];
        float w1 = W[(size_t)(k0 + kq * 4 + 1) * ldw + bn + m_l];
        float w2 = W[(size_t)(k0 + kq * 4 + 2) * ldw + bn + m_l];
        float w3 = W[(size_t)(k0 + kq * 4 + 3) * ldw + bn + m_l];
        __syncthreads();
        As[kq * 4 + 0][m_l] = av.x;
        As[kq * 4 + 1][m_l] = av.y;
        As[kq * 4 + 2][m_l] = av.z;
        As[kq * 4 + 3][m_l] = av.w;
        Wd[kq * 4 + 0][m_l] = make_float2(w0, w0);
        Wd[kq * 4 + 1][m_l] = make_float2(w1, w1);
        Wd[kq * 4 + 2][m_l] = make_float2(w2, w2);
        Wd[kq * 4 + 3][m_l] = make_float2(w3, w3);
        __syncthreads();
#pragma unroll
        for (int k = 0; k < 16; k++) {
            float2 a0 = *reinterpret_cast<const float2*>(&As[k][r0]);
            float2 a1 = *reinterpret_cast<const float2*>(&As[k][r0 + 2]);
#pragma unroll
            for (int c = 0; c < 4; c++) {
                float2 wv = Wd[k][c0 + c];
                acc[0][c] = fma2(a0, wv, acc[0][c]);
                acc[1][c] = fma2(a1, wv, acc[1][c]);
            }
        }
    }

#pragma unroll
    for (int c = 0; c < 4; c++) {
        int n = bn + c0 + c;
        float bv = bias ? bias[n] : 0.f;
        C[(size_t)(bm + r0 + 0) * N + n] = acc[0][c].x + bv;
        C[(size_t)(bm + r0 + 1) * N + n] = acc[0][c].y + bv;
        C[(size_t)(bm + r0 + 2) * N + n] = acc[1][c].x + bv;
        C[(size_t)(bm + r0 + 3) * N + n] = acc[1][c].y + bv;
    }
}

// ---------------------------------------------------------------------------
// Persistent encoder recurrence. ONE launch for all 40 steps.
// grid = 128 blocks x 128 threads; block bi owns u in [bi*8, bi*8+8)
// (24 output cols = 3 gates x 8). Wh slice (96KB) cached in shared once.
// Grid barrier between steps via global atomic counter + release epoch.
// NOTE: all shared strides EVEN so float2 LDS/STS.64 stay 8B-aligned.
// ---------------------------------------------------------------------------
#define ENC_BLOCKS 128
#define ENC_THREADS 128
#define WSH_FLOATS (1024 * 24)
#define HST_STRIDE 66
#define HST_BUF (32 * HST_STRIDE)
#define GHS_STRIDE 26
#define ENC_SMEM_FLOATS (WSH_FLOATS + 2 * HST_BUF + 64 * GHS_STRIDE)
#define ENC_SMEM_BYTES (ENC_SMEM_FLOATS * 4)

__global__ __launch_bounds__(ENC_THREADS, 1) void enc_persistent(
    const float* __restrict__ gxe,   // [B*S][3U]  (includes b0)
    const float* __restrict__ Wh,    // [U][3U]
    const float* __restrict__ b1,    // [3U]
    float* __restrict__ enc_out,     // [B*S][U]
    unsigned* bar_cnt, unsigned* bar_rel)
{
    extern __shared__ float sm[];
    float* Wsh  = sm;                              // [1024][24]
    float* hst  = sm + WSH_FLOATS;                 // [2][32][HST_STRIDE]
    float* ghsh = sm + WSH_FLOATS + 2 * HST_BUF;   // [64][GHS_STRIDE]

    const int tid = threadIdx.x;
    const int bi  = blockIdx.x;
    const int u0  = bi * 8;

    // Preload this block's Wh slice: Wsh[k][gate*8+du] = Wh[k][gate*1024+u0+du]
    for (int i = tid; i < WSH_FLOATS; i += ENC_THREADS) {
        int k = i / 24, c = i % 24;
        Wsh[i] = Wh[(size_t)k * G3 + (c >> 3) * UU + u0 + (c & 7)];
    }

    __shared__ unsigned relbase_s;
    if (tid == 0) relbase_s = *(volatile unsigned*)bar_rel;
    __syncthreads();
    const unsigned relbase = relbase_s;

    const int rg = tid >> 2;          // 0..31: rows 2rg, 2rg+1
    const int cg = tid & 3;           // col-pair group: cpairs cg*3..cg*3+2

    for (int t = 0; t < SS; t++) {
        if (t > 0) {
            // ---- grid barrier #t: wait until all blocks wrote h_{t-1} ----
            __threadfence();
            __syncthreads();
            if (tid == 0) {
                unsigned old = atomicAdd(bar_cnt, 1u);
                if (old == ENC_BLOCKS - 1) {
                    atomicExch(bar_cnt, 0u);
                    __threadfence();
                    atomicAdd(bar_rel, 1u);
                }
                while (*(volatile unsigned*)bar_rel - relbase < (unsigned)t) {}
            }
            __syncthreads();
            __threadfence();
        }

        float2 acc[2][3];
#pragma unroll
        for (int p = 0; p < 2; p++)
#pragma unroll
            for (int j = 0; j < 3; j++) acc[p][j] = make_float2(0.f, 0.f);

        if (t > 0) {
            const float* hprev = enc_out + (size_t)(t - 1) * UU;  // + b*SS*UU

            float4 pf[4];
            // prefetch chunk 0
#pragma unroll
            for (int q = 0; q < 4; q++) {
                int e = q * 128 + tid;
                int row = e >> 3, k4 = e & 7;
                pf[q] = *reinterpret_cast<const float4*>(
                    hprev + (size_t)row * (SS * UU) + k4 * 4);
            }
#pragma unroll
            for (int q = 0; q < 4; q++) {
                int e = q * 128 + tid;
                int row = e >> 3, k4 = e & 7;
                hst[(k4 * 4 + 0) * HST_STRIDE + row] = pf[q].x;
                hst[(k4 * 4 + 1) * HST_STRIDE + row] = pf[q].y;
                hst[(k4 * 4 + 2) * HST_STRIDE + row] = pf[q].z;
                hst[(k4 * 4 + 3) * HST_STRIDE + row] = pf[q].w;
            }
            __syncthreads();

            for (int c = 0; c < 32; c++) {
                if (c + 1 < 32) {
#pragma unroll
                    for (int q = 0; q < 4; q++) {
                        int e = q * 128 + tid;
                        int row = e >> 3, k4 = e & 7;
                        pf[q] = *reinterpret_cast<const float4*>(
                            hprev + (size_t)row * (SS * UU) + (c + 1) * 32 + k4 * 4);
                    }
                }
                const float* hb = hst + (c & 1) * HST_BUF;
                const float* wb = Wsh + (size_t)c * 32 * 24 + cg * 6;
#pragma unroll
                for (int kk = 0; kk < 32; kk++) {
                    float2 hp = *reinterpret_cast<const float2*>(hb + kk * HST_STRIDE + rg * 2);
                    float2 d0 = make_float2(hp.x, hp.x);
                    float2 d1 = make_float2(hp.y, hp.y);
                    const float* wr = wb + kk * 24;
                    float2 w0 = *reinterpret_cast<const float2*>(wr + 0);
                    float2 w1 = *reinterpret_cast<const float2*>(wr + 2);
                    float2 w2 = *reinterpret_cast<const float2*>(wr + 4);
                    acc[0][0] = fma2(d0, w0, acc[0][0]);
                    acc[1][0] = fma2(d1, w0, acc[1][0]);
                    acc[0][1] = fma2(d0, w1, acc[0][1]);
                    acc[1][1] = fma2(d1, w1, acc[1][1]);
                    acc[0][2] = fma2(d0, w2, acc[0][2]);
                    acc[1][2] = fma2(d1, w2, acc[1][2]);
                }
                if (c + 1 < 32) {
                    float* dst = hst + ((c + 1) & 1) * HST_BUF;
#pragma unroll
                    for (int q = 0; q < 4; q++) {
                        int e = q * 128 + tid;
                        int row = e >> 3, k4 = e & 7;
                        dst[(k4 * 4 + 0) * HST_STRIDE + row] = pf[q].x;
                        dst[(k4 * 4 + 1) * HST_STRIDE + row] = pf[q].y;
                        dst[(k4 * 4 + 2) * HST_STRIDE + row] = pf[q].z;
                        dst[(k4 * 4 + 3) * HST_STRIDE + row] = pf[q].w;
                    }
                    __syncthreads();
                }
            }

            // scatter gh to shared for epilogue regrouping
            __syncthreads();
#pragma unroll
            for (int j = 0; j < 3; j++) {
                int cp = cg * 3 + j;
                *reinterpret_cast<float2*>(ghsh + (2 * rg) * GHS_STRIDE + 2 * cp)     = acc[0][j];
                *reinterpret_cast<float2*>(ghsh + (2 * rg + 1) * GHS_STRIDE + 2 * cp) = acc[1][j];
            }
            __syncthreads();
        }

        // Epilogue: 4 (b,u) outputs per thread
        {
            int b = tid >> 1;
            const float* gxrow = gxe + (size_t)(b * SS + t) * G3;
#pragma unroll
            for (int j = 0; j < 4; j++) {
                int du = (tid & 1) * 4 + j;
                int u = u0 + du;
                float ghz = 0.f, ghr = 0.f, ghc = 0.f, hold = 0.f;
                if (t > 0) {
                    ghz = ghsh[b * GHS_STRIDE + du];
                    ghr = ghsh[b * GHS_STRIDE + 8 + du];
                    ghc = ghsh[b * GHS_STRIDE + 16 + du];
                    hold = enc_out[(size_t)(b * SS + t - 1) * UU + u];
                }
                float z = sigmoidf_(gxrow[u] + ghz + b1[u]);
                float r = sigmoidf_(gxrow[UU + u] + ghr + b1[UU + u]);
                float cc = tanhf(gxrow[2 * UU + u] + r * (ghc + b1[2 * UU + u]));
                enc_out[(size_t)(b * SS + t) * UU + u] = z * hold + (1.f - z) * cc;
            }
        }
    }
}

// ---------------------------------------------------------------------------
// Decoder step (one block per batch b, 256 threads):
//   scores = h . enc_out ; softmax ; gx_ctx = sum_s w_s * P[b,s,:] ; GRU(h0=0)
// ---------------------------------------------------------------------------
__global__ __launch_bounds__(256) void dec_step_kernel(
    const float* __restrict__ h_prev, int hp_stride,
    const float* __restrict__ enc_out,
    const float* __restrict__ P,
    const float* __restrict__ gxd_t, int gxd_stride,
    const float* __restrict__ db1,
    float* __restrict__ h_out, int ho_stride)
{
    const int b = blockIdx.x;
    const int tid = threadIdx.x;
    const int warp = tid >> 5, lane = tid & 31;

    __shared__ float wsm[SS];
    __shared__ float gxc[G3];

    {
        const float* hb = h_prev + (size_t)b * hp_stride;
        const float* eb = enc_out + (size_t)b * SS * UU;
        float acc[5] = {0.f, 0.f, 0.f, 0.f, 0.f};
#pragma unroll 4
        for (int i = 0; i < 32; i++) {
            int uidx = lane + 32 * i;
            float hv = hb[uidx];
#pragma unroll
            for (int q = 0; q < 5; q++)
                acc[q] += hv * eb[(size_t)(warp * 5 + q) * UU + uidx];
        }
#pragma unroll
        for (int q = 0; q < 5; q++) {
            float v = acc[q];
            for (int o = 16; o; o >>= 1) v += __shfl_xor_sync(0xffffffffu, v, o);
            if (lane == 0) wsm[warp * 5 + q] = v;
        }
    }
    __syncthreads();

    if (tid == 0) {
        float mx = -1e30f;
        for (int s = 0; s < SS; s++) mx = fmaxf(mx, wsm[s]);
        float sm = 0.f;
        for (int s = 0; s < SS; s++) { float e = expf(wsm[s] - mx); wsm[s] = e; sm += e; }
        float inv = 1.f / sm;
        for (int s = 0; s < SS; s++) wsm[s] *= inv;
    }
    __syncthreads();

    {
        const float* Pb = P + (size_t)b * SS * G3;
        float a[12];
#pragma unroll
        for (int i = 0; i < 12; i++) a[i] = 0.f;
        for (int s = 0; s < SS; s++) {
            float w = wsm[s];
            const float* row = Pb + (size_t)s * G3;
#pragma unroll
            for (int i = 0; i < 12; i++)
                a[i] += w * row[tid + i * 256];
        }
#pragma unroll
        for (int i = 0; i < 12; i++) gxc[tid + i * 256] = a[i];
    }
    __syncthreads();

    {
        const float* gx = gxd_t + (size_t)b * gxd_stride;
        float* ho = h_out + (size_t)b * ho_stride;
#pragma unroll
        for (int i = 0; i < 4; i++) {
            int u = tid + i * 256;
            float z = sigmoidf_(gxc[u] + gx[u] + db1[u]);
            float r = sigmoidf_(gxc[UU + u] + gx[UU + u] + db1[UU + u]);
            float c = tanhf(gxc[2 * UU + u] + gx[2 * UU + u] + r * db1[2 * UU + u]);
            ho[u] = (1.f - z) * c;
        }
    }
}

// ---------------------------------------------------------------------------
extern "C" void kernel_launch(void* const* d_in, const int* in_sizes, int n_in,
                              void* d_out, int out_size)
{
    const int*   inp     = (const int*)d_in[0];
    const int*   targ    = (const int*)d_in[1];
    const float* enc_emb = (const float*)d_in[2];
    const float* enc_Wx  = (const float*)d_in[3];
    const float* enc_Wh  = (const float*)d_in[4];
    const float* enc_b   = (const float*)d_in[5];
    const float* dec_emb = (const float*)d_in[6];
    const float* dec_Wx  = (const float*)d_in[7];
    // d_in[8] = dec_Wh: provably unused (decoder GRU hidden input is zeros)
    const float* dec_b   = (const float*)d_in[9];
    const float* fc_W    = (const float*)d_in[10];
    const float* fc_b    = (const float*)d_in[11];
    float* out = (float*)d_out;

    float *gxe, *gxd, *enc_out, *P, *hdec;
    unsigned* bar;
    cudaGetSymbolAddress((void**)&gxe,     g_gxe);
    cudaGetSymbolAddress((void**)&gxd,     g_gxd);
    cudaGetSymbolAddress((void**)&enc_out, g_enc_out);
    cudaGetSymbolAddress((void**)&P,       g_P);
    cudaGetSymbolAddress((void**)&hdec,    g_hdec);
    cudaGetSymbolAddress((void**)&bar,     g_bar);

    cudaFuncSetAttribute(enc_persistent,
                         cudaFuncAttributeMaxDynamicSharedMemorySize, ENC_SMEM_BYTES);

    // 1) Encoder gx for all timesteps: (B*S,3U) = emb[inp] @ enc_Wx + b0
    gemm_f32<<<dim3(G3 / 64, (BB * SS) / 64), 256>>>(
        nullptr, enc_emb, inp, SS, SS, EE,
        enc_Wx, G3, enc_b, gxe, BB * SS, G3, EE);

    // 2) Decoder xt-part gx for all steps: emb[targ[:, :-1]] @ dec_Wx[U:] + b0
    gemm_f32<<<dim3(G3 / 64, (BB * TD) / 64), 256>>>(
        nullptr, dec_emb, targ, TD, SS, EE,
        dec_Wx + (size_t)UU * G3, G3, dec_b, gxd, BB * TD, G3, EE);

    // 3) Encoder recurrence: ONE persistent kernel with grid barriers
    enc_persistent<<<ENC_BLOCKS, ENC_THREADS, ENC_SMEM_BYTES>>>(
        gxe, enc_Wh, enc_b + G3, enc_out, bar, bar + 1);

    // 4) P = enc_out @ dec_Wx[:U]   (factored attention-context projection)
    gemm_f32<<<dim3(G3 / 64, (BB * SS) / 64), 256>>>(
        enc_out, nullptr, nullptr, 1, 1, UU,
        dec_Wx, G3, nullptr, P, BB * SS, G3, UU);

    // 5) Decoder recurrence (sequential, cheap: attention + weighted sum + GRU)
    for (int t = 0; t < TD; t++) {
        const float* hp;
        int hps;
        if (t == 0) { hp = enc_out + (size_t)(SS - 1) * UU; hps = SS * UU; }
        else        { hp = hdec + (size_t)(t - 1) * UU;     hps = TD * UU; }
        dec_step_kernel<<<BB, 256>>>(
            hp, hps, enc_out, P,
            gxd + (size_t)t * G3, TD * G3,
            dec_b + G3,
            hdec + (size_t)t * UU, TD * UU);
    }

    // 6) Batched output projection: preds = hdec @ fc_W + fc_b
    gemm_f32<<<dim3(VV / 64, (BB * TD) / 64), 256>>>(
        hdec, nullptr, nullptr, 1, 1, UU,
        fc_W, VV, fc_b, out, BB * TD, VV, UU);
}

// round 6
// speedup vs baseline: 2.3908x; 1.7699x over previous
#include <cuda_runtime.h>
#include <math.h>
#include <stdint.h>
#include <string.h>

#define BB 64
#define SS 40
#define TD 39
#define EE 256
#define UU 1024
#define VV 8192
#define G3 3072

// Scratch (device globals; no allocation allowed)
static __device__ float g_gxe[BB * SS * G3];      // encoder x@Wx + b0
static __device__ float g_gxd[BB * TD * G3];      // decoder xt@Wx_bot + b0
static __device__ float g_enc_out[BB * SS * UU];  // encoder hidden sequence
static __device__ float g_P[BB * SS * G3];        // enc_out @ dec_Wx[:U]
static __device__ float g_hdec[BB * TD * UU];     // decoder hidden per step
static __device__ unsigned g_bar[2];              // [0]=count, [1]=release epoch

// ---------------------------------------------------------------------------
// packed fp32x2 FMA (2x FFMA pipe throughput on sm_103a)
// ---------------------------------------------------------------------------
__device__ __forceinline__ float2 fma2(float2 a, float2 b, float2 c) {
    unsigned long long ua, ub, uc;
    memcpy(&ua, &a, 8); memcpy(&ub, &b, 8); memcpy(&uc, &c, 8);
    asm("fma.rn.f32x2 %0, %1, %2, %0;" : "+l"(uc) : "l"(ua), "l"(ub));
    float2 r; memcpy(&r, &uc, 8);
    return r;
}

__device__ __forceinline__ float sigmoidf_(float x) {
    return 1.0f / (1.0f + expf(-x));
}

// ---------------------------------------------------------------------------
// fp32 GEMM v2:  C[M,N] = A[M,K] @ W[K,N] (+ bias)
// Optional row gather: A row m = emb[idx[(m/TT)*stride + m%TT]]
// 128x128 block tile, BK=16, 256 threads, 8x8 microtile, col-packed f32x2.
// LDS economy: 4 LDS.128 per 32 fma2 (A duplicated in REGISTERS, not smem).
// N multiple of 128; K multiple of 16; M arbitrary (clamped loads, guarded
// stores).
// ---------------------------------------------------------------------------
__global__ __launch_bounds__(256) void gemm_f32(
    const float* __restrict__ A,
    const float* __restrict__ emb, const int* __restrict__ idx,
    int idxTT, int idxStride, int lda,
    const float* __restrict__ W, int ldw,
    const float* __restrict__ bias,
    float* __restrict__ C, int M, int N, int K)
{
    __shared__ __align__(16) float As[16][128];
    __shared__ __align__(16) float Ws[16][128];

    const int tid = threadIdx.x;
    const int bm = blockIdx.y * 128;
    const int bn = blockIdx.x * 128;

    // A loader: row = bm + (tid&127), covers 8 k per thread (2 float4)
    const int arow_l = tid & 127;
    const int akq    = tid >> 7;       // 0..1 -> k offset 0 / 8
    {
    }
    int mload = bm + arow_l;
    if (mload >= M) mload = M - 1;     // clamp (store side is guarded)
    const float* arow;
    if (emb) {
        int r = idx[(mload / idxTT) * idxStride + (mload % idxTT)];
        arow = emb + (size_t)r * lda;
    } else {
        arow = A + (size_t)mload * lda;
    }

    // W loader: k rows (tid>>5) and (tid>>5)+8, 4 cols at (tid&31)*4
    const int wk = tid >> 5;           // 0..7
    const int wn = (tid & 31) * 4;

    const int tx = tid & 15, ty = tid >> 4;
    const int r0 = ty * 8, c0 = tx * 8;

    float2 acc[8][4];
#pragma unroll
    for (int r = 0; r < 8; r++)
#pragma unroll
        for (int c = 0; c < 4; c++) acc[r][c] = make_float2(0.f, 0.f);

    for (int k0 = 0; k0 < K; k0 += 16) {
        float4 av0 = *reinterpret_cast<const float4*>(arow + k0 + akq * 8);
        float4 av1 = *reinterpret_cast<const float4*>(arow + k0 + akq * 8 + 4);
        float4 wv0 = *reinterpret_cast<const float4*>(W + (size_t)(k0 + wk) * ldw + bn + wn);
        float4 wv1 = *reinterpret_cast<const float4*>(W + (size_t)(k0 + wk + 8) * ldw + bn + wn);
        __syncthreads();
        As[akq * 8 + 0][arow_l] = av0.x;
        As[akq * 8 + 1][arow_l] = av0.y;
        As[akq * 8 + 2][arow_l] = av0.z;
        As[akq * 8 + 3][arow_l] = av0.w;
        As[akq * 8 + 4][arow_l] = av1.x;
        As[akq * 8 + 5][arow_l] = av1.y;
        As[akq * 8 + 6][arow_l] = av1.z;
        As[akq * 8 + 7][arow_l] = av1.w;
        *reinterpret_cast<float4*>(&Ws[wk][wn])     = wv0;
        *reinterpret_cast<float4*>(&Ws[wk + 8][wn]) = wv1;
        __syncthreads();
#pragma unroll
        for (int k = 0; k < 16; k++) {
            float4 a0 = *reinterpret_cast<const float4*>(&As[k][r0]);
            float4 a1 = *reinterpret_cast<const float4*>(&As[k][r0 + 4]);
            float4 w0 = *reinterpret_cast<const float4*>(&Ws[k][c0]);
            float4 w1 = *reinterpret_cast<const float4*>(&Ws[k][c0 + 4]);
            float2 w[4];
            w[0] = make_float2(w0.x, w0.y);
            w[1] = make_float2(w0.z, w0.w);
            w[2] = make_float2(w1.x, w1.y);
            w[3] = make_float2(w1.z, w1.w);
            float ar[8] = {a0.x, a0.y, a0.z, a0.w, a1.x, a1.y, a1.z, a1.w};
#pragma unroll
            for (int r = 0; r < 8; r++) {
                float2 ad = make_float2(ar[r], ar[r]);
#pragma unroll
                for (int c = 0; c < 4; c++)
                    acc[r][c] = fma2(ad, w[c], acc[r][c]);
            }
        }
    }

    // Epilogue: 8 rows x 8 cols per thread, 2x STG.128 per row
    float bv[8];
#pragma unroll
    for (int j = 0; j < 8; j++) bv[j] = bias ? bias[bn + c0 + j] : 0.f;
#pragma unroll
    for (int r = 0; r < 8; r++) {
        int mrow = bm + r0 + r;
        if (mrow < M) {
            float4 o0, o1;
            o0.x = acc[r][0].x + bv[0];
            o0.y = acc[r][0].y + bv[1];
            o0.z = acc[r][1].x + bv[2];
            o0.w = acc[r][1].y + bv[3];
            o1.x = acc[r][2].x + bv[4];
            o1.y = acc[r][2].y + bv[5];
            o1.z = acc[r][3].x + bv[6];
            o1.w = acc[r][3].y + bv[7];
            *reinterpret_cast<float4*>(C + (size_t)mrow * N + bn + c0)     = o0;
            *reinterpret_cast<float4*>(C + (size_t)mrow * N + bn + c0 + 4) = o1;
        }
    }
}

// ---------------------------------------------------------------------------
// Persistent encoder recurrence. ONE launch for all 40 steps.
// grid = 128 blocks x 128 threads; block bi owns u in [bi*8, bi*8+8)
// (24 output cols = 3 gates x 8). Wh slice (96KB) cached in shared once.
// Grid barrier between steps via global atomic counter + release epoch.
// NOTE: all shared strides EVEN so float2 LDS/STS.64 stay 8B-aligned.
// ---------------------------------------------------------------------------
#define ENC_BLOCKS 128
#define ENC_THREADS 128
#define WSH_FLOATS (1024 * 24)
#define HST_STRIDE 66
#define HST_BUF (32 * HST_STRIDE)
#define GHS_STRIDE 26
#define ENC_SMEM_FLOATS (WSH_FLOATS + 2 * HST_BUF + 64 * GHS_STRIDE)
#define ENC_SMEM_BYTES (ENC_SMEM_FLOATS * 4)

__global__ __launch_bounds__(ENC_THREADS, 1) void enc_persistent(
    const float* __restrict__ gxe,   // [B*S][3U]  (includes b0)
    const float* __restrict__ Wh,    // [U][3U]
    const float* __restrict__ b1,    // [3U]
    float* __restrict__ enc_out,     // [B*S][U]
    unsigned* bar_cnt, unsigned* bar_rel)
{
    extern __shared__ float sm[];
    float* Wsh  = sm;                              // [1024][24]
    float* hst  = sm + WSH_FLOATS;                 // [2][32][HST_STRIDE]
    float* ghsh = sm + WSH_FLOATS + 2 * HST_BUF;   // [64][GHS_STRIDE]

    const int tid = threadIdx.x;
    const int bi  = blockIdx.x;
    const int u0  = bi * 8;

    // Preload this block's Wh slice: Wsh[k][gate*8+du] = Wh[k][gate*1024+u0+du]
    for (int i = tid; i < WSH_FLOATS; i += ENC_THREADS) {
        int k = i / 24, c = i % 24;
        Wsh[i] = Wh[(size_t)k * G3 + (c >> 3) * UU + u0 + (c & 7)];
    }

    __shared__ unsigned relbase_s;
    if (tid == 0) relbase_s = *(volatile unsigned*)bar_rel;
    __syncthreads();
    const unsigned relbase = relbase_s;

    const int rg = tid >> 2;          // 0..31: rows 2rg, 2rg+1
    const int cg = tid & 3;           // col-pair group: cpairs cg*3..cg*3+2

    for (int t = 0; t < SS; t++) {
        if (t > 0) {
            // ---- grid barrier #t: wait until all blocks wrote h_{t-1} ----
            __threadfence();
            __syncthreads();
            if (tid == 0) {
                unsigned old = atomicAdd(bar_cnt, 1u);
                if (old == ENC_BLOCKS - 1) {
                    atomicExch(bar_cnt, 0u);
                    __threadfence();
                    atomicAdd(bar_rel, 1u);
                }
                while (*(volatile unsigned*)bar_rel - relbase < (unsigned)t) {}
            }
            __syncthreads();
            __threadfence();
        }

        float2 acc[2][3];
#pragma unroll
        for (int p = 0; p < 2; p++)
#pragma unroll
            for (int j = 0; j < 3; j++) acc[p][j] = make_float2(0.f, 0.f);

        if (t > 0) {
            const float* hprev = enc_out + (size_t)(t - 1) * UU;  // + b*SS*UU

            float4 pf[4];
            // prefetch chunk 0
#pragma unroll
            for (int q = 0; q < 4; q++) {
                int e = q * 128 + tid;
                int row = e >> 3, k4 = e & 7;
                pf[q] = *reinterpret_cast<const float4*>(
                    hprev + (size_t)row * (SS * UU) + k4 * 4);
            }
#pragma unroll
            for (int q = 0; q < 4; q++) {
                int e = q * 128 + tid;
                int row = e >> 3, k4 = e & 7;
                hst[(k4 * 4 + 0) * HST_STRIDE + row] = pf[q].x;
                hst[(k4 * 4 + 1) * HST_STRIDE + row] = pf[q].y;
                hst[(k4 * 4 + 2) * HST_STRIDE + row] = pf[q].z;
                hst[(k4 * 4 + 3) * HST_STRIDE + row] = pf[q].w;
            }
            __syncthreads();

            for (int c = 0; c < 32; c++) {
                if (c + 1 < 32) {
#pragma unroll
                    for (int q = 0; q < 4; q++) {
                        int e = q * 128 + tid;
                        int row = e >> 3, k4 = e & 7;
                        pf[q] = *reinterpret_cast<const float4*>(
                            hprev + (size_t)row * (SS * UU) + (c + 1) * 32 + k4 * 4);
                    }
                }
                const float* hb = hst + (c & 1) * HST_BUF;
                const float* wb = Wsh + (size_t)c * 32 * 24 + cg * 6;
#pragma unroll
                for (int kk = 0; kk < 32; kk++) {
                    float2 hp = *reinterpret_cast<const float2*>(hb + kk * HST_STRIDE + rg * 2);
                    float2 d0 = make_float2(hp.x, hp.x);
                    float2 d1 = make_float2(hp.y, hp.y);
                    const float* wr = wb + kk * 24;
                    float2 w0 = *reinterpret_cast<const float2*>(wr + 0);
                    float2 w1 = *reinterpret_cast<const float2*>(wr + 2);
                    float2 w2 = *reinterpret_cast<const float2*>(wr + 4);
                    acc[0][0] = fma2(d0, w0, acc[0][0]);
                    acc[1][0] = fma2(d1, w0, acc[1][0]);
                    acc[0][1] = fma2(d0, w1, acc[0][1]);
                    acc[1][1] = fma2(d1, w1, acc[1][1]);
                    acc[0][2] = fma2(d0, w2, acc[0][2]);
                    acc[1][2] = fma2(d1, w2, acc[1][2]);
                }
                if (c + 1 < 32) {
                    float* dst = hst + ((c + 1) & 1) * HST_BUF;
#pragma unroll
                    for (int q = 0; q < 4; q++) {
                        int e = q * 128 + tid;
                        int row = e >> 3, k4 = e & 7;
                        dst[(k4 * 4 + 0) * HST_STRIDE + row] = pf[q].x;
                        dst[(k4 * 4 + 1) * HST_STRIDE + row] = pf[q].y;
                        dst[(k4 * 4 + 2) * HST_STRIDE + row] = pf[q].z;
                        dst[(k4 * 4 + 3) * HST_STRIDE + row] = pf[q].w;
                    }
                    __syncthreads();
                }
            }

            // scatter gh to shared for epilogue regrouping
            __syncthreads();
#pragma unroll
            for (int j = 0; j < 3; j++) {
                int cp = cg * 3 + j;
                *reinterpret_cast<float2*>(ghsh + (2 * rg) * GHS_STRIDE + 2 * cp)     = acc[0][j];
                *reinterpret_cast<float2*>(ghsh + (2 * rg + 1) * GHS_STRIDE + 2 * cp) = acc[1][j];
            }
            __syncthreads();
        }

        // Epilogue: 4 (b,u) outputs per thread
        {
            int b = tid >> 1;
            const float* gxrow = gxe + (size_t)(b * SS + t) * G3;
#pragma unroll
            for (int j = 0; j < 4; j++) {
                int du = (tid & 1) * 4 + j;
                int u = u0 + du;
                float ghz = 0.f, ghr = 0.f, ghc = 0.f, hold = 0.f;
                if (t > 0) {
                    ghz = ghsh[b * GHS_STRIDE + du];
                    ghr = ghsh[b * GHS_STRIDE + 8 + du];
                    ghc = ghsh[b * GHS_STRIDE + 16 + du];
                    hold = enc_out[(size_t)(b * SS + t - 1) * UU + u];
                }
                float z = sigmoidf_(gxrow[u] + ghz + b1[u]);
                float r = sigmoidf_(gxrow[UU + u] + ghr + b1[UU + u]);
                float cc = tanhf(gxrow[2 * UU + u] + r * (ghc + b1[2 * UU + u]));
                enc_out[(size_t)(b * SS + t) * UU + u] = z * hold + (1.f - z) * cc;
            }
        }
    }
}

// ---------------------------------------------------------------------------
// Decoder step (one block per batch b, 256 threads):
//   scores = h . enc_out ; softmax ; gx_ctx = sum_s w_s * P[b,s,:] ; GRU(h0=0)
// ---------------------------------------------------------------------------
__global__ __launch_bounds__(256) void dec_step_kernel(
    const float* __restrict__ h_prev, int hp_stride,
    const float* __restrict__ enc_out,
    const float* __restrict__ P,
    const float* __restrict__ gxd_t, int gxd_stride,
    const float* __restrict__ db1,
    float* __restrict__ h_out, int ho_stride)
{
    const int b = blockIdx.x;
    const int tid = threadIdx.x;
    const int warp = tid >> 5, lane = tid & 31;

    __shared__ float wsm[SS];
    __shared__ float gxc[G3];

    {
        const float* hb = h_prev + (size_t)b * hp_stride;
        const float* eb = enc_out + (size_t)b * SS * UU;
        float acc[5] = {0.f, 0.f, 0.f, 0.f, 0.f};
#pragma unroll 4
        for (int i = 0; i < 32; i++) {
            int uidx = lane + 32 * i;
            float hv = hb[uidx];
#pragma unroll
            for (int q = 0; q < 5; q++)
                acc[q] += hv * eb[(size_t)(warp * 5 + q) * UU + uidx];
        }
#pragma unroll
        for (int q = 0; q < 5; q++) {
            float v = acc[q];
            for (int o = 16; o; o >>= 1) v += __shfl_xor_sync(0xffffffffu, v, o);
            if (lane == 0) wsm[warp * 5 + q] = v;
        }
    }
    __syncthreads();

    if (tid == 0) {
        float mx = -1e30f;
        for (int s = 0; s < SS; s++) mx = fmaxf(mx, wsm[s]);
        float sm = 0.f;
        for (int s = 0; s < SS; s++) { float e = expf(wsm[s] - mx); wsm[s] = e; sm += e; }
        float inv = 1.f / sm;
        for (int s = 0; s < SS; s++) wsm[s] *= inv;
    }
    __syncthreads();

    {
        const float* Pb = P + (size_t)b * SS * G3;
        float a[12];
#pragma unroll
        for (int i = 0; i < 12; i++) a[i] = 0.f;
        for (int s = 0; s < SS; s++) {
            float w = wsm[s];
            const float* row = Pb + (size_t)s * G3;
#pragma unroll
            for (int i = 0; i < 12; i++)
                a[i] += w * row[tid + i * 256];
        }
#pragma unroll
        for (int i = 0; i < 12; i++) gxc[tid + i * 256] = a[i];
    }
    __syncthreads();

    {
        const float* gx = gxd_t + (size_t)b * gxd_stride;
        float* ho = h_out + (size_t)b * ho_stride;
#pragma unroll
        for (int i = 0; i < 4; i++) {
            int u = tid + i * 256;
            float z = sigmoidf_(gxc[u] + gx[u] + db1[u]);
            float r = sigmoidf_(gxc[UU + u] + gx[UU + u] + db1[UU + u]);
            float c = tanhf(gxc[2 * UU + u] + gx[2 * UU + u] + r * db1[2 * UU + u]);
            ho[u] = (1.f - z) * c;
        }
    }
}

// ---------------------------------------------------------------------------
extern "C" void kernel_launch(void* const* d_in, const int* in_sizes, int n_in,
                              void* d_out, int out_size)
{
    const int*   inp     = (const int*)d_in[0];
    const int*   targ    = (const int*)d_in[1];
    const float* enc_emb = (const float*)d_in[2];
    const float* enc_Wx  = (const float*)d_in[3];
    const float* enc_Wh  = (const float*)d_in[4];
    const float* enc_b   = (const float*)d_in[5];
    const float* dec_emb = (const float*)d_in[6];
    const float* dec_Wx  = (const float*)d_in[7];
    // d_in[8] = dec_Wh: provably unused (decoder GRU hidden input is zeros)
    const float* dec_b   = (const float*)d_in[9];
    const float* fc_W    = (const float*)d_in[10];
    const float* fc_b    = (const float*)d_in[11];
    float* out = (float*)d_out;

    float *gxe, *gxd, *enc_out, *P, *hdec;
    unsigned* bar;
    cudaGetSymbolAddress((void**)&gxe,     g_gxe);
    cudaGetSymbolAddress((void**)&gxd,     g_gxd);
    cudaGetSymbolAddress((void**)&enc_out, g_enc_out);
    cudaGetSymbolAddress((void**)&P,       g_P);
    cudaGetSymbolAddress((void**)&hdec,    g_hdec);
    cudaGetSymbolAddress((void**)&bar,     g_bar);

    cudaFuncSetAttribute(enc_persistent,
                         cudaFuncAttributeMaxDynamicSharedMemorySize, ENC_SMEM_BYTES);

    // 1) Encoder gx for all timesteps: (B*S,3U) = emb[inp] @ enc_Wx + b0
    gemm_f32<<<dim3(G3 / 128, (BB * SS + 127) / 128), 256>>>(
        nullptr, enc_emb, inp, SS, SS, EE,
        enc_Wx, G3, enc_b, gxe, BB * SS, G3, EE);

    // 2) Decoder xt-part gx for all steps: emb[targ[:, :-1]] @ dec_Wx[U:] + b0
    gemm_f32<<<dim3(G3 / 128, (BB * TD + 127) / 128), 256>>>(
        nullptr, dec_emb, targ, TD, SS, EE,
        dec_Wx + (size_t)UU * G3, G3, dec_b, gxd, BB * TD, G3, EE);

    // 3) Encoder recurrence: ONE persistent kernel with grid barriers
    enc_persistent<<<ENC_BLOCKS, ENC_THREADS, ENC_SMEM_BYTES>>>(
        gxe, enc_Wh, enc_b + G3, enc_out, bar, bar + 1);

    // 4) P = enc_out @ dec_Wx[:U]   (factored attention-context projection)
    gemm_f32<<<dim3(G3 / 128, (BB * SS + 127) / 128), 256>>>(
        enc_out, nullptr, nullptr, 1, 1, UU,
        dec_Wx, G3, nullptr, P, BB * SS, G3, UU);

    // 5) Decoder recurrence (sequential, cheap: attention + weighted sum + GRU)
    for (int t = 0; t < TD; t++) {
        const float* hp;
        int hps;
        if (t == 0) { hp = enc_out + (size_t)(SS - 1) * UU; hps = SS * UU; }
        else        { hp = hdec + (size_t)(t - 1) * UU;     hps = TD * UU; }
        dec_step_kernel<<<BB, 256>>>(
            hp, hps, enc_out, P,
            gxd + (size_t)t * G3, TD * G3,
            dec_b + G3,
            hdec + (size_t)t * UU, TD * UU);
    }

    // 6) Batched output projection: preds = hdec @ fc_W + fc_b
    gemm_f32<<<dim3(VV / 128, (BB * TD + 127) / 128), 256>>>(
        hdec, nullptr, nullptr, 1, 1, UU,
        fc_W, VV, fc_b, out, BB * TD, VV, UU);
}